// round 17
// baseline (speedup 1.0000x reference)
#include <cuda_runtime.h>

#define NB 4
#define NK 128
#define NG 128

// ---- output layout (float32, tuple flattened & concatenated) ----
#define OFF_ROIS    0
#define OFF_OBJ     2048
#define OFF_DELTAS  526336
#define OFF_RANKS   528384
#define OFF_SPATIAL 528896

// Per-image sync state, one 128B line each (zero-initialized; the 128th
// done-arriver of each image resets it for the next launch).
struct __align__(128) ImgSync {
    unsigned long long pos[2];   // 128 positive bits
    int arrive;                  // arrival counter (release-add), target 128
    int done;                    // post-read counter; 128th resets everything
    int pad[26];
};
__device__ ImgSync g_sync[NB];

// grid = 256, block = 256. Block g owns sources sA=2g, sB=2g+1 of image
// b = sA>>7. Warps 0-3 -> A, warps 4-7 -> B (argmax: lane lt = GT lt).
// BARRIER-FREE PUBLISH: warp 0 (A) / warp 4 (B) alone scan all 128 GTs
// with the division-free test (3*inter >= ap+ag, == iou>=0.5), ballot,
// and lane 0 publishes pos bit + arrival count immediately — no smem, no
// __syncthreads on the publish path. Argmax/deltas/box overlap the wait.
__global__ void __launch_bounds__(256) fused_kernel(
    const float* __restrict__ proposals,
    const float* __restrict__ obj_feat,
    const float* __restrict__ gt_boxes,
    const int*   __restrict__ gt_ranks,
    float*       __restrict__ out)
{
    const int g    = blockIdx.x;
    const int sA   = g * 2;
    const int sB   = sA + 1;
    const int b    = sA >> 7;
    const int t    = threadIdx.x;
    const int side = t >> 7;          // 0 = proposal A, 1 = proposal B
    const int lt   = t & 127;
    const int w    = t >> 5;          // warp id 0..7
    const int lane = t & 31;

    // ---- publish-critical loads FIRST (ahead of payload queue traffic) ----
    const int s = side ? sB : sA;
    const int p = s & 127;
    const float4 pr = ((const float4*)proposals)[s];            // broadcast
    const float4 gt = ((const float4*)gt_boxes)[(b << 7) + lt]; // argmax GT

    // pos-scan warps (0 and 4): 3 extra GTs per lane (latency-parallel)
    const bool scanw = (lt < 32);
    float4 gt1, gt2, gt3;
    if (scanw) {
        gt1 = ((const float4*)gt_boxes)[(b << 7) + lane + 32];
        gt2 = ((const float4*)gt_boxes)[(b << 7) + lane + 64];
        gt3 = ((const float4*)gt_boxes)[(b << 7) + lane + 96];
    }

    // ---- payload loads LAST: needed only at the final scatter ----
    const float4 payA = ((const float4*)obj_feat)[(size_t)sA * 256 + t];
    const float4 payB = ((const float4*)obj_feat)[(size_t)sB * 256 + t];

    __shared__ float s_bi[8], s_bu[8];
    __shared__ int   s_bj[8];
    __shared__ int   s_pos[2];
    __shared__ int   s_dest[2];
    __shared__ int4  s_box[2];

    const float ap = (pr.z - pr.x) * (pr.w - pr.y);

    // ---- barrier-free pos + publish (warps 0 and 4 only) ----
    int pos = 0;
    if (scanw) {
        // division-free test: iou >= 0.5  <=>  3*inter >= ap + ag
        float best = -1.0f;
        {
            const float dy = fminf(pr.z, gt.z) - fmaxf(pr.x, gt.x);
            const float dx = fminf(pr.w, gt.w) - fmaxf(pr.y, gt.y);
            const float inter = fmaxf(dx, 0.0f) * fmaxf(dy, 0.0f);
            best = fmaxf(best, 3.0f * inter - (ap + (gt.z - gt.x) * (gt.w - gt.y)));
        }
        {
            const float dy = fminf(pr.z, gt1.z) - fmaxf(pr.x, gt1.x);
            const float dx = fminf(pr.w, gt1.w) - fmaxf(pr.y, gt1.y);
            const float inter = fmaxf(dx, 0.0f) * fmaxf(dy, 0.0f);
            best = fmaxf(best, 3.0f * inter - (ap + (gt1.z - gt1.x) * (gt1.w - gt1.y)));
        }
        {
            const float dy = fminf(pr.z, gt2.z) - fmaxf(pr.x, gt2.x);
            const float dx = fminf(pr.w, gt2.w) - fmaxf(pr.y, gt2.y);
            const float inter = fmaxf(dx, 0.0f) * fmaxf(dy, 0.0f);
            best = fmaxf(best, 3.0f * inter - (ap + (gt2.z - gt2.x) * (gt2.w - gt2.y)));
        }
        {
            const float dy = fminf(pr.z, gt3.z) - fmaxf(pr.x, gt3.x);
            const float dx = fminf(pr.w, gt3.w) - fmaxf(pr.y, gt3.y);
            const float inter = fmaxf(dx, 0.0f) * fmaxf(dy, 0.0f);
            best = fmaxf(best, 3.0f * inter - (ap + (gt3.z - gt3.x) * (gt3.w - gt3.y)));
        }
        const unsigned m = __ballot_sync(0xFFFFFFFFu, best >= 0.0f);
        pos = (m != 0u);
        if (lane == 0) {
            s_pos[side] = pos;
            ImgSync* S = &g_sync[b];
            if (pos) {
                const unsigned long long bit = 1ULL << (p & 63);
                asm volatile("red.relaxed.gpu.global.or.b64 [%0], %1;"
                             :: "l"(&S->pos[p >> 6]), "l"(bit) : "memory");
            }
            int one = 1;
            asm volatile("red.release.gpu.global.add.s32 [%0], %1;"
                         :: "l"(&S->arrive), "r"(one) : "memory");
        }
    }

    // ---- argmax (all 8 warps; lane lt handles GT index lt) ----
    {
        const float dy = fminf(pr.z, gt.z) - fmaxf(pr.x, gt.x);
        const float dx = fminf(pr.w, gt.w) - fmaxf(pr.y, gt.y);
        float bi = fmaxf(dx, 0.0f) * fmaxf(dy, 0.0f);
        float bu = ap + (gt.z - gt.x) * (gt.w - gt.y) - bi;
        int   bj = lt;
        // shfl_down partner has HIGHER gt index; strict > keeps first max
        #pragma unroll
        for (int off = 16; off; off >>= 1) {
            const float oi = __shfl_down_sync(0xFFFFFFFFu, bi, off);
            const float ou = __shfl_down_sync(0xFFFFFFFFu, bu, off);
            const int   oj = __shfl_down_sync(0xFFFFFFFFu, bj, off);
            if (oi * bu > bi * ou) { bi = oi; bu = ou; bj = oj; }
        }
        if (lane == 0) { s_bi[w] = bi; s_bu[w] = bu; s_bj[w] = bj; }
    }
    __syncthreads();

    // ---- leaders (t=0, t=128): merge, precompute, wait, dest, scalars ----
    if (lt == 0) {
        const int mypos = s_pos[side];
        const int w0 = side * 4;
        float mbi = s_bi[w0], mbu = s_bu[w0];
        int   mbj = s_bj[w0];
        #pragma unroll
        for (int ww = 1; ww < 4; ww++)
            if (s_bi[w0 + ww] * mbu > mbi * s_bu[w0 + ww]) {
                mbi = s_bi[w0 + ww]; mbu = s_bu[w0 + ww]; mbj = s_bj[w0 + ww];
            }

        const float4 gb = ((const float4*)gt_boxes)[(b << 7) + mbj];
        float gy1 = gb.x, gx1 = gb.y, gy2 = gb.z, gx2 = gb.w;
        float4 dl = make_float4(0.f, 0.f, 0.f, 0.f);
        float rk = 0.0f;
        if (mypos) {
            const float h  = pr.z - pr.x, wd = pr.w - pr.y;
            const float cy = pr.x + 0.5f * h, cx = pr.y + 0.5f * wd;
            const float gh = gy2 - gy1, gw = gx2 - gx1;
            const float gcy = gy1 + 0.5f * gh, gcx = gx1 + 0.5f * gw;
            dl.x = ((gcy - cy) / h)  / 0.1f;
            dl.y = ((gcx - cx) / wd) / 0.1f;
            dl.z = logf(gh / h)  / 0.2f;
            dl.w = logf(gw / wd) / 0.2f;
            rk = (float)gt_ranks[b * NG + mbj];
        } else {
            gy1 = gx1 = gy2 = gx2 = 0.0f;    // roi_gt = 0 for negatives
        }
        int4 box;
        {
            // integer spatial box (window transform + denorm + round-half-even)
            const float win0 = 128.0f / 1023.0f;
            const float win2 = 895.0f / 1023.0f;
            const float wsc  = win2 - win0;
            int by1 = (int)rintf(((gy1 - win0) / wsc) * 479.0f);
            int bx1 = (int)rintf(gx1 * 639.0f);
            int by2 = (int)rintf(((gy2 - win0) / wsc) * 479.0f + 1.0f);
            int bx2 = (int)rintf(gx2 * 639.0f + 1.0f);
            if (!((by2 - by1) * (bx2 - bx1) > 0)) { by1 = bx1 = by2 = bx2 = 0; }
            box = make_int4(by1, bx1, by2, bx2);
        }

        // ---- wait: single-word relaxed polls, acquire on completion ----
        ImgSync* S = &g_sync[b];
        int av;
        int spins = 0;
        for (;;) {
            asm volatile("ld.relaxed.gpu.global.b32 %0, [%1];"
                         : "=r"(av) : "l"(&S->arrive) : "memory");
            if (av == NK) break;
            if (++spins > 128) __nanosleep(32);
        }
        asm volatile("ld.acquire.gpu.global.b32 %0, [%1];"
                     : "=r"(av) : "l"(&S->arrive) : "memory");
        unsigned long long p0, p1;
        asm volatile("ld.relaxed.gpu.global.b64 %0, [%1];"
                     : "=l"(p0) : "l"(&S->pos[0]) : "memory");
        asm volatile("ld.relaxed.gpu.global.b64 %0, [%1];"
                     : "=l"(p1) : "l"(&S->pos[1]) : "memory");

        const int npos = __popcll(p0) + __popcll(p1);
        const unsigned long long bit = 1ULL << (p & 63);
        const unsigned long long myw = (p < 64) ? p0 : p1;
        int below = __popcll(myw & (bit - 1));
        if (p >= 64) below += __popcll(p0);
        const int dest = mypos ? below : (npos + (p - below));
        const int dbo  = (b << 7) + dest;

        // done counter; the 128th arriver resets this image's sync
        int old, one = 1;
        asm volatile("atom.release.gpu.global.add.s32 %0, [%1], %2;"
                     : "=r"(old) : "l"(&S->done), "r"(one) : "memory");
        if (old == NK - 1) {
            const unsigned long long z = 0ULL;
            asm volatile("st.relaxed.gpu.global.b64 [%0], %1;" :: "l"(&S->pos[0]), "l"(z) : "memory");
            asm volatile("st.relaxed.gpu.global.b64 [%0], %1;" :: "l"(&S->pos[1]), "l"(z) : "memory");
            int zi = 0;
            asm volatile("st.relaxed.gpu.global.b32 [%0], %1;" :: "l"(&S->arrive), "r"(zi) : "memory");
            asm volatile("st.relaxed.gpu.global.b32 [%0], %1;" :: "l"(&S->done),   "r"(zi) : "memory");
        }

        // scalar outputs for this ROI
        ((float4*)(out + OFF_ROIS))[dbo]   = pr;
        ((float4*)(out + OFF_DELTAS))[dbo] = dl;
        out[OFF_RANKS + dbo] = rk;

        s_dest[side] = dest;
        s_box[side]  = box;
    }
    __syncthreads();

    // ---- scatter: both payloads + analytic spatial maps ----
    const int dboA = (b << 7) + s_dest[0];
    const int dboB = (b << 7) + s_dest[1];
    const int4 bxA = s_box[0];
    const int4 bxB = s_box[1];

    ((float4*)(out + OFF_OBJ))[(size_t)dboA * 256 + t] = payA;
    ((float4*)(out + OFF_OBJ))[(size_t)dboB * 256 + t] = payB;

    // analytic spatial: thread t writes float4 covering elements [4t, 4t+4)
    const int row  = t >> 3;
    const int col0 = (t & 7) * 4;
    float4 vA = make_float4(0.f, 0.f, 0.f, 0.f);
    float4 vB = make_float4(0.f, 0.f, 0.f, 0.f);
    if (row >= 4 && row < 28) {
        const int r1 = 20 * (row - 4) + 9;
        const float fyA = (float)((bxA.x < r1)     && (r1     < bxA.z))
                        + (float)((bxA.x < r1 + 1) && (r1 + 1 < bxA.z));
        const float fyB = (float)((bxB.x < r1)     && (r1     < bxB.z))
                        + (float)((bxB.x < r1 + 1) && (r1 + 1 < bxB.z));
        const float scA = 0.25f * fyA;
        const float scB = 0.25f * fyB;
        float* pA = &vA.x;
        float* pB = &vB.x;
        #pragma unroll
        for (int k = 0; k < 4; k++) {
            const int c1 = 20 * (col0 + k) + 9;
            const float fxA = (float)((bxA.y < c1)     && (c1     < bxA.w))
                            + (float)((bxA.y < c1 + 1) && (c1 + 1 < bxA.w));
            const float fxB = (float)((bxB.y < c1)     && (c1     < bxB.w))
                            + (float)((bxB.y < c1 + 1) && (c1 + 1 < bxB.w));
            pA[k] = scA * fxA;
            pB[k] = scB * fxB;
        }
    }
    ((float4*)(out + OFF_SPATIAL))[(size_t)dboA * 256 + t] = vA;
    ((float4*)(out + OFF_SPATIAL))[(size_t)dboB * 256 + t] = vB;
}

extern "C" void kernel_launch(void* const* d_in, const int* in_sizes, int n_in,
                              void* d_out, int out_size)
{
    const float* proposals = (const float*)d_in[0];
    const float* obj_feat  = (const float*)d_in[1];
    const float* gt_boxes  = (const float*)d_in[2];
    const int*   gt_ranks  = (const int*)  d_in[3];
    float* out = (float*)d_out;

    fused_kernel<<<256, 256>>>(proposals, obj_feat, gt_boxes, gt_ranks, out);
}